// round 1
// baseline (speedup 1.0000x reference)
#include <cuda_runtime.h>
#include <math.h>

#define HID 4096
#define HEADS 32
#define DDIM 128
#define IDIM (HEADS * DDIM)            // 4096
#define QKV_ROWS (3 * IDIM)            // 12288
#define TOTAL_ROWS (QKV_ROWS + IDIM + HEADS + HEADS)  // 16448
#define EPS 1e-6f

// ---------------- scratch (no allocation allowed) ----------------
__device__ float g_qkv[QKV_ROWS];
__device__ float g_z[IDIM];
__device__ float g_ab[2 * HEADS];      // a[0:32], b[32:64]
__device__ float g_pre[IDIM];
__device__ float g_state_scratch[HEADS * DDIM * DDIM];   // fallback if out_size small
__device__ float g_conv_scratch[QKV_ROWS * 3];

// ---------------- kernel 1: fused matvec (qkv, z, a, b) ----------------
// one warp per output row; h (4096 f32) staged in shared
__global__ __launch_bounds__(256) void k_matvec_in(
    const float* __restrict__ Wqkv, const float* __restrict__ Wz,
    const float* __restrict__ Wa,   const float* __restrict__ Wb,
    const float* __restrict__ h)
{
    __shared__ float4 hs[HID / 4];
    const float4* h4 = reinterpret_cast<const float4*>(h);
    for (int i = threadIdx.x; i < HID / 4; i += 256) hs[i] = h4[i];
    __syncthreads();

    int warp = threadIdx.x >> 5;
    int lane = threadIdx.x & 31;
    int row  = blockIdx.x * 8 + warp;
    if (row >= TOTAL_ROWS) return;

    const float* W;
    float* outp;
    if (row < QKV_ROWS)              { W = Wqkv + (size_t)row * HID;              outp = g_qkv + row; }
    else if (row < QKV_ROWS + IDIM)  { int r = row - QKV_ROWS; W = Wz + (size_t)r * HID; outp = g_z + r; }
    else if (row < QKV_ROWS + IDIM + HEADS) { int r = row - QKV_ROWS - IDIM; W = Wa + (size_t)r * HID; outp = g_ab + r; }
    else                             { int r = row - QKV_ROWS - IDIM - HEADS; W = Wb + (size_t)r * HID; outp = g_ab + HEADS + r; }

    const float4* w4 = reinterpret_cast<const float4*>(W);
    float acc = 0.f;
#pragma unroll 8
    for (int i = 0; i < HID / 4 / 32; i++) {
        float4 w = w4[lane + i * 32];
        float4 x = hs[lane + i * 32];
        acc += w.x * x.x + w.y * x.y + w.z * x.z + w.w * x.w;
    }
#pragma unroll
    for (int o = 16; o; o >>= 1) acc += __shfl_down_sync(0xFFFFFFFFu, acc, o);
    if (lane == 0) *outp = acc;
}

// ---------------- kernel 2: conv + gating + state update ----------------
__device__ __forceinline__ float siluf(float x) { return x / (1.f + expf(-x)); }

__device__ __forceinline__ float block_reduce_sum_128(float v, float* red) {
    // 128 threads = 4 warps
#pragma unroll
    for (int o = 16; o; o >>= 1) v += __shfl_down_sync(0xFFFFFFFFu, v, o);
    int warp = threadIdx.x >> 5, lane = threadIdx.x & 31;
    if (lane == 0) red[warp] = v;
    __syncthreads();
    float s = red[0] + red[1] + red[2] + red[3];
    __syncthreads();
    return s;
}

__global__ __launch_bounds__(128) void k_state(
    const float* __restrict__ rnn_state, const float* __restrict__ conv_state,
    const float* __restrict__ conv_w,    const float* __restrict__ conv_b,
    const float* __restrict__ A_log,     const float* __restrict__ dt_bias,
    const float* __restrict__ norm_w,
    float* __restrict__ state_out,       float* __restrict__ conv_out)
{
    const int h = blockIdx.x;
    const int t = threadIdx.x;   // column index e, also d-index for channel

    __shared__ float kn_sh[DDIM];
    __shared__ float qn_sh[DDIM];
    __shared__ float red[4];

    // --- conv + silu for this head's q,k,v channels ---
    auto conv_ch = [&](int c) -> float {
        float x = g_qkv[c];
        const float* cs = conv_state + (size_t)c * 3;
        const float* cw = conv_w + (size_t)c * 4;
        float y = cs[0] * cw[0] + cs[1] * cw[1] + cs[2] * cw[2] + x * cw[3] + conv_b[c];
        // shifted conv state
        float* co = conv_out + (size_t)c * 3;
        co[0] = cs[1]; co[1] = cs[2]; co[2] = x;
        return siluf(y);
    };
    int cq = h * DDIM + t;
    float q = conv_ch(cq);
    float k = conv_ch(IDIM + cq);
    float v = conv_ch(2 * IDIM + cq);

    // --- l2 norms ---
    float sq = block_reduce_sum_128(q * q, red);
    float sk = block_reduce_sum_128(k * k, red);
    float qn = q / fmaxf(sqrtf(sq), EPS) * 0.08838834764831845f;  // 1/sqrt(128)
    float kn = k / fmaxf(sqrtf(sk), EPS);
    kn_sh[t] = kn;
    qn_sh[t] = qn;

    // --- scalars ---
    float aval = g_ab[h];
    float bval = g_ab[HEADS + h];
    float beta = 1.f / (1.f + expf(-bval));
    float arg  = aval + dt_bias[h];
    float sp   = (arg > 20.f) ? arg : log1pf(expf(arg));
    float decay = expf(-expf(A_log[h]) * sp);
    __syncthreads();

    // --- pass 1: kv_mem[e] = decay * sum_d S[d][e]*kn[d] ---
    const float* S = rnn_state + (size_t)h * DDIM * DDIM;
    float kv = 0.f;
#pragma unroll 4
    for (int d = 0; d < DDIM; d++) kv += S[d * DDIM + t] * kn_sh[d];
    kv *= decay;
    float delta = (v - kv) * beta;

    // --- pass 2: update state, accumulate core ---
    float* So = state_out + (size_t)h * DDIM * DDIM;
    float core = 0.f;
#pragma unroll 4
    for (int d = 0; d < DDIM; d++) {
        float s = S[d * DDIM + t] * decay + kn_sh[d] * delta;
        So[d * DDIM + t] = s;
        core += s * qn_sh[d];
    }

    // --- RMS norm over e + gate ---
    float var = block_reduce_sum_128(core * core, red) * (1.f / 128.f);
    core = norm_w[t] * core * rsqrtf(var + EPS);
    g_pre[h * DDIM + t] = core * siluf(g_z[h * DDIM + t]);
}

// ---------------- kernel 3: output matvec ----------------
__global__ __launch_bounds__(256) void k_matvec_out(
    const float* __restrict__ Wout, float* __restrict__ out)
{
    __shared__ float4 hs[IDIM / 4];
    const float4* p4 = reinterpret_cast<const float4*>(g_pre);
    for (int i = threadIdx.x; i < IDIM / 4; i += 256) hs[i] = p4[i];
    __syncthreads();

    int warp = threadIdx.x >> 5;
    int lane = threadIdx.x & 31;
    int row  = blockIdx.x * 8 + warp;
    if (row >= HID) return;

    const float4* w4 = reinterpret_cast<const float4*>(Wout + (size_t)row * IDIM);
    float acc = 0.f;
#pragma unroll 8
    for (int i = 0; i < IDIM / 4 / 32; i++) {
        float4 w = w4[lane + i * 32];
        float4 x = hs[lane + i * 32];
        acc += w.x * x.x + w.y * x.y + w.z * x.z + w.w * x.w;
    }
#pragma unroll
    for (int o = 16; o; o >>= 1) acc += __shfl_down_sync(0xFFFFFFFFu, acc, o);
    if (lane == 0) out[row] = acc;
}

// ---------------- launch ----------------
extern "C" void kernel_launch(void* const* d_in, const int* in_sizes, int n_in,
                              void* d_out, int out_size)
{
    const float* hidden     = (const float*)d_in[0];
    const float* rnn_state  = (const float*)d_in[1];
    const float* conv_state = (const float*)d_in[2];
    const float* W_qkv      = (const float*)d_in[3];
    const float* W_z        = (const float*)d_in[4];
    const float* W_a        = (const float*)d_in[5];
    const float* W_b        = (const float*)d_in[6];
    const float* conv_w     = (const float*)d_in[7];
    const float* conv_b     = (const float*)d_in[8];
    const float* A_log      = (const float*)d_in[9];
    const float* dt_bias    = (const float*)d_in[10];
    const float* norm_w     = (const float*)d_in[11];
    const float* W_out      = (const float*)d_in[12];

    float* out = (float*)d_out;

    // tuple outputs concatenated: out(4096) | state(524288) | new_conv_state(36864)
    float* state_out;
    float* conv_out;
    if (out_size >= IDIM + HEADS * DDIM * DDIM + QKV_ROWS * 3) {
        state_out = out + IDIM;
        conv_out  = out + IDIM + HEADS * DDIM * DDIM;
    } else {
        // unexpected layout: keep side outputs in scratch so main output still works
        cudaGetSymbolAddress((void**)&state_out, g_state_scratch);
        cudaGetSymbolAddress((void**)&conv_out,  g_conv_scratch);
    }

    k_matvec_in<<<(TOTAL_ROWS + 7) / 8, 256>>>(W_qkv, W_z, W_a, W_b, hidden);
    k_state<<<HEADS, 128>>>(rnn_state, conv_state, conv_w, conv_b,
                            A_log, dt_bias, norm_w, state_out, conv_out);
    k_matvec_out<<<HID / 8, 256>>>(W_out, out);
}

// round 2
// speedup vs baseline: 1.2428x; 1.2428x over previous
#include <cuda_runtime.h>
#include <math.h>

#define HID 4096
#define HEADS 32
#define DDIM 128
#define IDIM (HEADS * DDIM)            // 4096
#define QKV_ROWS (3 * IDIM)            // 12288
#define TOTAL_ROWS (QKV_ROWS + IDIM + HEADS + HEADS)  // 16448
#define EPS 1e-6f

// ---------------- scratch (no allocation allowed) ----------------
__device__ float g_qkv[QKV_ROWS];
__device__ float g_z[IDIM];
__device__ float g_ab[2 * HEADS];      // a[0:32], b[32:64]
__device__ float g_pre[IDIM];
__device__ float g_state_scratch[HEADS * DDIM * DDIM];   // fallback if out_size small
__device__ float g_conv_scratch[QKV_ROWS * 3];

__device__ __forceinline__ float siluf(float x) { return x / (1.f + expf(-x)); }

// ---------------- kernel 1: fused matvec (qkv, z, a, b) ----------------
// one warp per output row; h (4096 f32) staged in shared
__global__ __launch_bounds__(256) void k_matvec_in(
    const float* __restrict__ Wqkv, const float* __restrict__ Wz,
    const float* __restrict__ Wa,   const float* __restrict__ Wb,
    const float* __restrict__ h)
{
    __shared__ float4 hs[HID / 4];
    const float4* h4 = reinterpret_cast<const float4*>(h);
    for (int i = threadIdx.x; i < HID / 4; i += 256) hs[i] = h4[i];
    __syncthreads();

    int warp = threadIdx.x >> 5;
    int lane = threadIdx.x & 31;
    int row  = blockIdx.x * 8 + warp;
    if (row >= TOTAL_ROWS) return;

    const float* W;
    float* outp;
    if (row < QKV_ROWS)              { W = Wqkv + (size_t)row * HID;              outp = g_qkv + row; }
    else if (row < QKV_ROWS + IDIM)  { int r = row - QKV_ROWS; W = Wz + (size_t)r * HID; outp = g_z + r; }
    else if (row < QKV_ROWS + IDIM + HEADS) { int r = row - QKV_ROWS - IDIM; W = Wa + (size_t)r * HID; outp = g_ab + r; }
    else                             { int r = row - QKV_ROWS - IDIM - HEADS; W = Wb + (size_t)r * HID; outp = g_ab + HEADS + r; }

    const float4* w4 = reinterpret_cast<const float4*>(W) + lane;
    float acc0 = 0.f, acc1 = 0.f;
#pragma unroll
    for (int i = 0; i < 16; i++) {
        float4 wa = __ldcs(w4 + (2 * i) * 32);
        float4 wb = __ldcs(w4 + (2 * i + 1) * 32);
        float4 xa = hs[lane + (2 * i) * 32];
        float4 xb = hs[lane + (2 * i + 1) * 32];
        acc0 += wa.x * xa.x + wa.y * xa.y + wa.z * xa.z + wa.w * xa.w;
        acc1 += wb.x * xb.x + wb.y * xb.y + wb.z * xb.z + wb.w * xb.w;
    }
    float acc = acc0 + acc1;
#pragma unroll
    for (int o = 16; o; o >>= 1) acc += __shfl_down_sync(0xFFFFFFFFu, acc, o);
    if (lane == 0) *outp = acc;
}

// ---------------- kernel 2: conv + gating + state update ----------------
// 32 blocks (one per head) x 512 threads: dg = threadIdx>>7 in [0,4) covers
// 32 d-rows each; e = threadIdx&127 is the state column. Warp lanes span
// consecutive e -> fully coalesced 128B state loads/stores.
__global__ __launch_bounds__(512) void k_state(
    const float* __restrict__ rnn_state, const float* __restrict__ conv_state,
    const float* __restrict__ conv_w,    const float* __restrict__ conv_b,
    const float* __restrict__ A_log,     const float* __restrict__ dt_bias,
    const float* __restrict__ norm_w,
    float* __restrict__ state_out,       float* __restrict__ conv_out)
{
    const int h  = blockIdx.x;
    const int t  = threadIdx.x;
    const int e  = t & 127;
    const int dg = t >> 7;          // 0..3
    const int warp = t >> 5, lane = t & 31;

    __shared__ float kn_sh[DDIM];
    __shared__ float qn_sh[DDIM];
    __shared__ float delta_sh[DDIM];
    __shared__ float part[4][DDIM];
    __shared__ float red[16];

    float q = 0.f, k = 0.f, v = 0.f;
    if (dg == 0) {
        // conv + silu for this head's q,k,v channels (thread e -> channel d=e)
        auto conv_ch = [&](int c) -> float {
            float x = g_qkv[c];
            const float* cs = conv_state + (size_t)c * 3;
            const float* cw = conv_w + (size_t)c * 4;
            float y = cs[0] * cw[0] + cs[1] * cw[1] + cs[2] * cw[2] + x * cw[3] + conv_b[c];
            float* co = conv_out + (size_t)c * 3;
            co[0] = cs[1]; co[1] = cs[2]; co[2] = x;
            return siluf(y);
        };
        int cq = h * DDIM + e;
        q = conv_ch(cq);
        k = conv_ch(IDIM + cq);
        v = conv_ch(2 * IDIM + cq);
    }
    // norms: warps 0..3 hold q,k; others contribute zeros
    float sq = q * q, sk = k * k;
#pragma unroll
    for (int o = 16; o; o >>= 1) {
        sq += __shfl_down_sync(0xFFFFFFFFu, sq, o);
        sk += __shfl_down_sync(0xFFFFFFFFu, sk, o);
    }
    if (lane == 0) { red[warp] = sq; red[warp + 8] = sk; }
    __syncthreads();
    float sqt = red[0] + red[1] + red[2] + red[3];
    float skt = red[8] + red[9] + red[10] + red[11];
    if (dg == 0) {
        qn_sh[e] = q / fmaxf(sqrtf(sqt), EPS) * 0.08838834764831845f;  // 1/sqrt(128)
        kn_sh[e] = k / fmaxf(sqrtf(skt), EPS);
    }

    // scalars (computed redundantly, cheap)
    float beta  = 1.f / (1.f + expf(-g_ab[HEADS + h]));
    float arg   = g_ab[h] + dt_bias[h];
    float sp    = (arg > 20.f) ? arg : log1pf(expf(arg));
    float decay = expf(-expf(A_log[h]) * sp);
    __syncthreads();

    // pass 1: partial kv over this thread's 32 d-rows
    const float* S = rnn_state + (size_t)h * DDIM * DDIM;
    float kv = 0.f;
#pragma unroll
    for (int j = 0; j < 32; j++) {
        int d = dg * 32 + j;
        kv += S[d * DDIM + e] * kn_sh[d];
    }
    part[dg][e] = kv;
    __syncthreads();
    if (dg == 0) {
        float kvt = (part[0][e] + part[1][e] + part[2][e] + part[3][e]) * decay;
        delta_sh[e] = (v - kvt) * beta;
    }
    __syncthreads();

    // pass 2: update state (reads hit L2), accumulate partial core
    float* So = state_out + (size_t)h * DDIM * DDIM;
    float delta = delta_sh[e];
    float core = 0.f;
#pragma unroll
    for (int j = 0; j < 32; j++) {
        int d = dg * 32 + j;
        float s = S[d * DDIM + e] * decay + kn_sh[d] * delta;
        So[d * DDIM + e] = s;
        core += s * qn_sh[d];
    }
    part[dg][e] = core;
    __syncthreads();

    float c = 0.f;
    if (dg == 0) c = part[0][e] + part[1][e] + part[2][e] + part[3][e];
    float cc = c * c;
#pragma unroll
    for (int o = 16; o; o >>= 1) cc += __shfl_down_sync(0xFFFFFFFFu, cc, o);
    if (lane == 0) red[warp] = cc;
    __syncthreads();
    float var = (red[0] + red[1] + red[2] + red[3]) * (1.f / 128.f);
    if (dg == 0) {
        float cn = norm_w[e] * c * rsqrtf(var + EPS);
        g_pre[h * DDIM + e] = cn * siluf(g_z[h * DDIM + e]);
    }
}

// ---------------- kernel 3: output matvec ----------------
__global__ __launch_bounds__(256) void k_matvec_out(
    const float* __restrict__ Wout, float* __restrict__ out)
{
    __shared__ float4 hs[IDIM / 4];
    const float4* p4 = reinterpret_cast<const float4*>(g_pre);
    for (int i = threadIdx.x; i < IDIM / 4; i += 256) hs[i] = p4[i];
    __syncthreads();

    int warp = threadIdx.x >> 5;
    int lane = threadIdx.x & 31;
    int row  = blockIdx.x * 8 + warp;
    if (row >= HID) return;

    const float4* w4 = reinterpret_cast<const float4*>(Wout + (size_t)row * IDIM) + lane;
    float acc0 = 0.f, acc1 = 0.f;
#pragma unroll
    for (int i = 0; i < 16; i++) {
        float4 wa = __ldcs(w4 + (2 * i) * 32);
        float4 wb = __ldcs(w4 + (2 * i + 1) * 32);
        float4 xa = hs[lane + (2 * i) * 32];
        float4 xb = hs[lane + (2 * i + 1) * 32];
        acc0 += wa.x * xa.x + wa.y * xa.y + wa.z * xa.z + wa.w * xa.w;
        acc1 += wb.x * xb.x + wb.y * xb.y + wb.z * xb.z + wb.w * xb.w;
    }
    float acc = acc0 + acc1;
#pragma unroll
    for (int o = 16; o; o >>= 1) acc += __shfl_down_sync(0xFFFFFFFFu, acc, o);
    if (lane == 0) out[row] = acc;
}

// ---------------- launch ----------------
extern "C" void kernel_launch(void* const* d_in, const int* in_sizes, int n_in,
                              void* d_out, int out_size)
{
    const float* hidden     = (const float*)d_in[0];
    const float* rnn_state  = (const float*)d_in[1];
    const float* conv_state = (const float*)d_in[2];
    const float* W_qkv      = (const float*)d_in[3];
    const float* W_z        = (const float*)d_in[4];
    const float* W_a        = (const float*)d_in[5];
    const float* W_b        = (const float*)d_in[6];
    const float* conv_w     = (const float*)d_in[7];
    const float* conv_b     = (const float*)d_in[8];
    const float* A_log      = (const float*)d_in[9];
    const float* dt_bias    = (const float*)d_in[10];
    const float* norm_w     = (const float*)d_in[11];
    const float* W_out      = (const float*)d_in[12];

    float* out = (float*)d_out;

    // tuple outputs concatenated: out(4096) | state(524288) | new_conv_state(36864)
    float* state_out;
    float* conv_out;
    if (out_size >= IDIM + HEADS * DDIM * DDIM + QKV_ROWS * 3) {
        state_out = out + IDIM;
        conv_out  = out + IDIM + HEADS * DDIM * DDIM;
    } else {
        cudaGetSymbolAddress((void**)&state_out, g_state_scratch);
        cudaGetSymbolAddress((void**)&conv_out,  g_conv_scratch);
    }

    k_matvec_in<<<(TOTAL_ROWS + 7) / 8, 256>>>(W_qkv, W_z, W_a, W_b, hidden);
    k_state<<<HEADS, 512>>>(rnn_state, conv_state, conv_w, conv_b,
                            A_log, dt_bias, norm_w, state_out, conv_out);
    k_matvec_out<<<HID / 8, 256>>>(W_out, out);
}

// round 3
// speedup vs baseline: 1.2881x; 1.0365x over previous
#include <cuda_runtime.h>
#include <math.h>

#define HID 4096
#define HEADS 32
#define DDIM 128
#define IDIM (HEADS * DDIM)            // 4096
#define QKV_ROWS (3 * IDIM)            // 12288
#define TOTAL_ROWS (QKV_ROWS + IDIM + HEADS + HEADS)  // 16448
#define EPS 1e-6f

// ---------------- scratch (no allocation allowed) ----------------
__device__ float g_qkv[QKV_ROWS];
__device__ float g_z[IDIM];
__device__ float g_ab[2 * HEADS];      // a[0:32], b[32:64]
__device__ float g_pre[IDIM];
__device__ float g_state_scratch[HEADS * DDIM * DDIM];
__device__ float g_conv_scratch[QKV_ROWS * 3];

__device__ __forceinline__ float siluf(float x) { return x / (1.f + expf(-x)); }

__device__ __forceinline__ float dot4(float4 a, float4 b) {
    return a.x * b.x + a.y * b.y + a.z * b.z + a.w * b.w;
}

// ---------------- kernel 1: fused matvec (qkv, z, a, b) ----------------
// one warp per output row; h staged in shared; 4-deep pipelined LDG.128
__global__ __launch_bounds__(256) void k_matvec_in(
    const float* __restrict__ Wqkv, const float* __restrict__ Wz,
    const float* __restrict__ Wa,   const float* __restrict__ Wb,
    const float* __restrict__ h)
{
    __shared__ float4 hs[HID / 4];
    const float4* h4 = reinterpret_cast<const float4*>(h);
    for (int i = threadIdx.x; i < HID / 4; i += 256) hs[i] = h4[i];
    __syncthreads();

    int warp = threadIdx.x >> 5;
    int lane = threadIdx.x & 31;
    int row  = blockIdx.x * 8 + warp;
    if (row >= TOTAL_ROWS) return;

    const float* W;
    float* outp;
    if (row < QKV_ROWS)              { W = Wqkv + (size_t)row * HID;              outp = g_qkv + row; }
    else if (row < QKV_ROWS + IDIM)  { int r = row - QKV_ROWS; W = Wz + (size_t)r * HID; outp = g_z + r; }
    else if (row < QKV_ROWS + IDIM + HEADS) { int r = row - QKV_ROWS - IDIM; W = Wa + (size_t)r * HID; outp = g_ab + r; }
    else                             { int r = row - QKV_ROWS - IDIM - HEADS; W = Wb + (size_t)r * HID; outp = g_ab + HEADS + r; }

    const float4* w4 = reinterpret_cast<const float4*>(W) + lane;

    // 32 chunks of float4 per lane; process in 8 batches of 4 with prefetch
    float4 buf[4];
#pragma unroll
    for (int j = 0; j < 4; j++) buf[j] = __ldcs(w4 + j * 32);

    float a0 = 0.f, a1 = 0.f, a2 = 0.f, a3 = 0.f;
#pragma unroll
    for (int i = 0; i < 8; i++) {
        float4 c0 = buf[0], c1 = buf[1], c2 = buf[2], c3 = buf[3];
        if (i < 7) {
#pragma unroll
            for (int j = 0; j < 4; j++) buf[j] = __ldcs(w4 + ((i + 1) * 4 + j) * 32);
        }
        a0 += dot4(c0, hs[lane + (i * 4 + 0) * 32]);
        a1 += dot4(c1, hs[lane + (i * 4 + 1) * 32]);
        a2 += dot4(c2, hs[lane + (i * 4 + 2) * 32]);
        a3 += dot4(c3, hs[lane + (i * 4 + 3) * 32]);
    }
    float acc = (a0 + a1) + (a2 + a3);
#pragma unroll
    for (int o = 16; o; o >>= 1) acc += __shfl_down_sync(0xFFFFFFFFu, acc, o);
    if (lane == 0) *outp = acc;
}

// ---------------- kernel 2: conv + gating + state update (float4) -------
// 32 blocks x 512 threads = 16 d-groups x 32 lanes. Lane owns float4 of
// e-columns; each group covers 8 d-rows per pass.
__global__ __launch_bounds__(512) void k_state(
    const float* __restrict__ rnn_state, const float* __restrict__ conv_state,
    const float* __restrict__ conv_w,    const float* __restrict__ conv_b,
    const float* __restrict__ A_log,     const float* __restrict__ dt_bias,
    const float* __restrict__ norm_w,
    float* __restrict__ state_out,       float* __restrict__ conv_out)
{
    const int h    = blockIdx.x;
    const int t    = threadIdx.x;
    const int lane = t & 31;
    const int grp  = t >> 5;           // 0..15

    __shared__ float  kn_sh[DDIM];
    __shared__ float  qn_sh[DDIM];
    __shared__ float  v_sh[DDIM];
    __shared__ float4 part[16][32];
    __shared__ float4 delta4_sh[32];
    __shared__ float  red[32];

    // --- conv + silu: threads t<128, channel d = t ---
    float q = 0.f, k = 0.f, v = 0.f;
    if (t < DDIM) {
        auto conv_ch = [&](int c) -> float {
            float x = g_qkv[c];
            const float* cs = conv_state + (size_t)c * 3;
            const float* cw = conv_w + (size_t)c * 4;
            float y = cs[0] * cw[0] + cs[1] * cw[1] + cs[2] * cw[2] + x * cw[3] + conv_b[c];
            float* co = conv_out + (size_t)c * 3;
            co[0] = cs[1]; co[1] = cs[2]; co[2] = x;
            return siluf(y);
        };
        int cq = h * DDIM + t;
        q = conv_ch(cq);
        k = conv_ch(IDIM + cq);
        v = conv_ch(2 * IDIM + cq);
        v_sh[t] = v;
    }
    // --- l2 norms (warps 0..3 carry data) ---
    float sq = q * q, sk = k * k;
#pragma unroll
    for (int o = 16; o; o >>= 1) {
        sq += __shfl_down_sync(0xFFFFFFFFu, sq, o);
        sk += __shfl_down_sync(0xFFFFFFFFu, sk, o);
    }
    if (lane == 0) { red[grp] = sq; red[grp + 16] = sk; }
    __syncthreads();
    float sqt = red[0] + red[1] + red[2] + red[3];
    float skt = red[16] + red[17] + red[18] + red[19];
    if (t < DDIM) {
        qn_sh[t] = q / fmaxf(sqrtf(sqt), EPS) * 0.08838834764831845f;  // 1/sqrt(128)
        kn_sh[t] = k / fmaxf(sqrtf(skt), EPS);
    }

    // --- per-head scalars (redundant per thread, cheap) ---
    float beta  = 1.f / (1.f + expf(-g_ab[HEADS + h]));
    float arg   = g_ab[h] + dt_bias[h];
    float sp    = (arg > 20.f) ? arg : log1pf(expf(arg));
    float decay = expf(-expf(A_log[h]) * sp);
    __syncthreads();

    // --- pass 1: kv partials ---
    const float4* S4 = reinterpret_cast<const float4*>(rnn_state + (size_t)h * DDIM * DDIM);
    float4 kv = make_float4(0.f, 0.f, 0.f, 0.f);
#pragma unroll
    for (int j = 0; j < 8; j++) {
        int d = grp * 8 + j;
        float4 s = S4[d * 32 + lane];
        float kd = kn_sh[d];
        kv.x += s.x * kd; kv.y += s.y * kd; kv.z += s.z * kd; kv.w += s.w * kd;
    }
    part[grp][lane] = kv;
    __syncthreads();

    if (t < 32) {
        float4 kvt = make_float4(0.f, 0.f, 0.f, 0.f);
#pragma unroll
        for (int g = 0; g < 16; g++) {
            float4 p = part[g][lane];
            kvt.x += p.x; kvt.y += p.y; kvt.z += p.z; kvt.w += p.w;
        }
        float4 d4;
        d4.x = (v_sh[lane * 4 + 0] - kvt.x * decay) * beta;
        d4.y = (v_sh[lane * 4 + 1] - kvt.y * decay) * beta;
        d4.z = (v_sh[lane * 4 + 2] - kvt.z * decay) * beta;
        d4.w = (v_sh[lane * 4 + 3] - kvt.w * decay) * beta;
        delta4_sh[lane] = d4;
    }
    __syncthreads();

    // --- pass 2: update state, partial core ---
    float4* So4 = reinterpret_cast<float4*>(state_out + (size_t)h * DDIM * DDIM);
    float4 delta = delta4_sh[lane];
    float4 core = make_float4(0.f, 0.f, 0.f, 0.f);
#pragma unroll
    for (int j = 0; j < 8; j++) {
        int d = grp * 8 + j;
        float4 s = S4[d * 32 + lane];
        float kd = kn_sh[d], qd = qn_sh[d];
        s.x = s.x * decay + kd * delta.x;
        s.y = s.y * decay + kd * delta.y;
        s.z = s.z * decay + kd * delta.z;
        s.w = s.w * decay + kd * delta.w;
        So4[d * 32 + lane] = s;
        core.x += s.x * qd; core.y += s.y * qd; core.z += s.z * qd; core.w += s.w * qd;
    }
    part[grp][lane] = core;
    __syncthreads();

    // --- single-warp RMS norm + gate ---
    if (t < 32) {
        float4 c = make_float4(0.f, 0.f, 0.f, 0.f);
#pragma unroll
        for (int g = 0; g < 16; g++) {
            float4 p = part[g][lane];
            c.x += p.x; c.y += p.y; c.z += p.z; c.w += p.w;
        }
        float cc = c.x * c.x + c.y * c.y + c.z * c.z + c.w * c.w;
#pragma unroll
        for (int o = 16; o; o >>= 1) cc += __shfl_xor_sync(0xFFFFFFFFu, cc, o);
        float inv = rsqrtf(cc * (1.f / 128.f) + EPS);
        const float4 nw = reinterpret_cast<const float4*>(norm_w)[lane];
        const float4 z4 = reinterpret_cast<const float4*>(g_z + h * DDIM)[lane];
        float4 o4;
        o4.x = nw.x * c.x * inv * siluf(z4.x);
        o4.y = nw.y * c.y * inv * siluf(z4.y);
        o4.z = nw.z * c.z * inv * siluf(z4.z);
        o4.w = nw.w * c.w * inv * siluf(z4.w);
        reinterpret_cast<float4*>(g_pre + h * DDIM)[lane] = o4;
    }
}

// ---------------- kernel 3: output matvec ----------------
__global__ __launch_bounds__(256) void k_matvec_out(
    const float* __restrict__ Wout, float* __restrict__ out)
{
    __shared__ float4 hs[IDIM / 4];
    const float4* p4 = reinterpret_cast<const float4*>(g_pre);
    for (int i = threadIdx.x; i < IDIM / 4; i += 256) hs[i] = p4[i];
    __syncthreads();

    int warp = threadIdx.x >> 5;
    int lane = threadIdx.x & 31;
    int row  = blockIdx.x * 8 + warp;
    if (row >= HID) return;

    const float4* w4 = reinterpret_cast<const float4*>(Wout + (size_t)row * IDIM) + lane;

    float4 buf[4];
#pragma unroll
    for (int j = 0; j < 4; j++) buf[j] = __ldcs(w4 + j * 32);

    float a0 = 0.f, a1 = 0.f, a2 = 0.f, a3 = 0.f;
#pragma unroll
    for (int i = 0; i < 8; i++) {
        float4 c0 = buf[0], c1 = buf[1], c2 = buf[2], c3 = buf[3];
        if (i < 7) {
#pragma unroll
            for (int j = 0; j < 4; j++) buf[j] = __ldcs(w4 + ((i + 1) * 4 + j) * 32);
        }
        a0 += dot4(c0, hs[lane + (i * 4 + 0) * 32]);
        a1 += dot4(c1, hs[lane + (i * 4 + 1) * 32]);
        a2 += dot4(c2, hs[lane + (i * 4 + 2) * 32]);
        a3 += dot4(c3, hs[lane + (i * 4 + 3) * 32]);
    }
    float acc = (a0 + a1) + (a2 + a3);
#pragma unroll
    for (int o = 16; o; o >>= 1) acc += __shfl_down_sync(0xFFFFFFFFu, acc, o);
    if (lane == 0) out[row] = acc;
}

// ---------------- launch ----------------
extern "C" void kernel_launch(void* const* d_in, const int* in_sizes, int n_in,
                              void* d_out, int out_size)
{
    const float* hidden     = (const float*)d_in[0];
    const float* rnn_state  = (const float*)d_in[1];
    const float* conv_state = (const float*)d_in[2];
    const float* W_qkv      = (const float*)d_in[3];
    const float* W_z        = (const float*)d_in[4];
    const float* W_a        = (const float*)d_in[5];
    const float* W_b        = (const float*)d_in[6];
    const float* conv_w     = (const float*)d_in[7];
    const float* conv_b     = (const float*)d_in[8];
    const float* A_log      = (const float*)d_in[9];
    const float* dt_bias    = (const float*)d_in[10];
    const float* norm_w     = (const float*)d_in[11];
    const float* W_out      = (const float*)d_in[12];

    float* out = (float*)d_out;

    float* state_out;
    float* conv_out;
    if (out_size >= IDIM + HEADS * DDIM * DDIM + QKV_ROWS * 3) {
        state_out = out + IDIM;
        conv_out  = out + IDIM + HEADS * DDIM * DDIM;
    } else {
        cudaGetSymbolAddress((void**)&state_out, g_state_scratch);
        cudaGetSymbolAddress((void**)&conv_out,  g_conv_scratch);
    }

    k_matvec_in<<<(TOTAL_ROWS + 7) / 8, 256>>>(W_qkv, W_z, W_a, W_b, hidden);
    k_state<<<HEADS, 512>>>(rnn_state, conv_state, conv_w, conv_b,
                            A_log, dt_bias, norm_w, state_out, conv_out);
    k_matvec_out<<<HID / 8, 256>>>(W_out, out);
}